// round 9
// baseline (speedup 1.0000x reference)
#include <cuda_runtime.h>
#include <math.h>

// LIANetLight hash-grid encoder.
// Inputs (metadata order):
//  0: x0      float32 [B]
//  1: y0      float32 [B]
//  2: tables  float32 [T, 2]
//  3: seeds   uint32  [L]
//  4: level_N float32 [L]
//  5: memorized_crop_size (scalar)
//  6: complete_tile_size  (scalar)
// Output: float32 [B, L*2, H, W]

#define HASH_P1 2654435761u
#define HASH_P2 805459861u

__device__ __forceinline__ float read_scalar_as_float(const int* p) {
    int v = *p;
    if (v > 0 && v < (1 << 24)) return (float)v;
    return __int_as_float(v);
}

// ---------------------------------------------------------------------------
// Direct kernel, 2 pixels per thread: (h, w) and (h + H/2, w).
// The x-side (xn, fx, ix0, hx0, hx1) is shared by the pair; 8 table gathers
// in flight per level per thread. Seed is folded into the y-hashes AFTER the
// +P2 increment (XOR does not commute with the additive increment trick).
// Warp = 32 consecutive w -> fully coalesced stores. No barriers.
// Requires: H even, T power of two, L == 16.
// ---------------------------------------------------------------------------
__global__ void __launch_bounds__(256)
hashenc_2px(const float* __restrict__ x0,
            const float* __restrict__ y0,
            const float2* __restrict__ tables,
            const unsigned int* __restrict__ seeds,
            const float* __restrict__ levelN,
            const int* __restrict__ tile_ptr,
            float* __restrict__ out,
            int H, unsigned int mask)
{
    const int L = 16;

    __shared__ float s_scale[16];
    __shared__ unsigned int s_seed[16];
    if (threadIdx.x < L) {
        const float tf = read_scalar_as_float(tile_ptr);
        s_scale[threadIdx.x] = levelN[threadIdx.x] / tf;
        s_seed[threadIdx.x]  = seeds[threadIdx.x];
    }
    __syncthreads();

    const int H2 = H >> 1;
    const int HW = H * H;
    const int perb = H2 * H;

    const int b   = blockIdx.y;
    const int idx = (int)(blockIdx.x * blockDim.x + threadIdx.x);
    if (idx >= perb) return;

    const int h1 = idx / H;            // 0..H/2-1
    const int w  = idx - h1 * H;       // 0..H-1

    const float ox = x0[b];
    const float oy = y0[b];
    const float px  = (float)w  + ox;
    const float py1 = (float)h1 + oy;
    const float py2 = (float)(h1 + H2) + oy;

    float* outb1 = out + (size_t)b * (size_t)(2 * L) * (size_t)HW
                       + (size_t)h1 * (size_t)H + w;
    float* outb2 = outb1 + (size_t)H2 * (size_t)H;

    #pragma unroll
    for (int l = 0; l < L; l++) {
        const float sc        = s_scale[l];
        const unsigned int se = s_seed[l];

        // shared x-chain (seed NOT folded here: hx1 derives by +P1)
        const float xn  = px * sc;
        const float fxf = floorf(xn);
        const float fx  = xn - fxf;
        const float gx  = 1.0f - fx;
        const unsigned int hx0 = (unsigned int)(int)fxf * HASH_P1;
        const unsigned int hx1 = hx0 + HASH_P1;   // (ix0+1)*P1 mod 2^32

        // pixel 1 y-chain; seed folded AFTER the +P2 increment
        const float yn1  = py1 * sc;
        const float fyf1 = floorf(yn1);
        const float fy1  = yn1 - fyf1;
        unsigned int hy0a = (unsigned int)(int)fyf1 * HASH_P2;
        unsigned int hy1a = hy0a + HASH_P2;
        hy0a ^= se;  hy1a ^= se;

        // pixel 2 y-chain
        const float yn2  = py2 * sc;
        const float fyf2 = floorf(yn2);
        const float fy2  = yn2 - fyf2;
        unsigned int hy0b = (unsigned int)(int)fyf2 * HASH_P2;
        unsigned int hy1b = hy0b + HASH_P2;
        hy0b ^= se;  hy1b ^= se;

        // 8 independent gathers in flight
        const float2 a00 = __ldg(&tables[(hx0 ^ hy0a) & mask]);
        const float2 a10 = __ldg(&tables[(hx1 ^ hy0a) & mask]);
        const float2 a01 = __ldg(&tables[(hx0 ^ hy1a) & mask]);
        const float2 a11 = __ldg(&tables[(hx1 ^ hy1a) & mask]);
        const float2 b00 = __ldg(&tables[(hx0 ^ hy0b) & mask]);
        const float2 b10 = __ldg(&tables[(hx1 ^ hy0b) & mask]);
        const float2 b01 = __ldg(&tables[(hx0 ^ hy1b) & mask]);
        const float2 b11 = __ldg(&tables[(hx1 ^ hy1b) & mask]);

        // pixel 1 interpolation
        {
            const float gy = 1.0f - fy1;
            const float w00 = gx * gy, w10 = fx * gy;
            const float w01 = gx * fy1, w11 = fx * fy1;
            const float ex = w00 * a00.x + w10 * a10.x + w01 * a01.x + w11 * a11.x;
            const float ey = w00 * a00.y + w10 * a10.y + w01 * a01.y + w11 * a11.y;
            outb1[(size_t)(2 * l)     * (size_t)HW] = ex;
            outb1[(size_t)(2 * l + 1) * (size_t)HW] = ey;
        }
        // pixel 2 interpolation
        {
            const float gy = 1.0f - fy2;
            const float w00 = gx * gy, w10 = fx * gy;
            const float w01 = gx * fy2, w11 = fx * fy2;
            const float ex = w00 * b00.x + w10 * b10.x + w01 * b01.x + w11 * b11.x;
            const float ey = w00 * b00.y + w10 * b10.y + w01 * b01.y + w11 * b11.y;
            outb2[(size_t)(2 * l)     * (size_t)HW] = ex;
            outb2[(size_t)(2 * l + 1) * (size_t)HW] = ey;
        }
    }
}

// ---------------------------------------------------------------------------
// Generic fallback (round-1 kernel): one thread per pixel.
// ---------------------------------------------------------------------------
template <int LFIX, bool POW2>
__global__ void __launch_bounds__(256)
hashenc_kernel(const float* __restrict__ x0,
               const float* __restrict__ y0,
               const float2* __restrict__ tables,
               const unsigned int* __restrict__ seeds,
               const float* __restrict__ levelN,
               const int* __restrict__ tile_ptr,
               float* __restrict__ out,
               int B, int H, int Lrt,
               unsigned int T, unsigned int mask)
{
    const int L = (LFIX > 0) ? LFIX : Lrt;

    __shared__ float s_scale[64];
    __shared__ unsigned int s_seed[64];
    if (threadIdx.x < L) {
        float tf = read_scalar_as_float(tile_ptr);
        s_scale[threadIdx.x] = levelN[threadIdx.x] / tf;
        s_seed[threadIdx.x]  = seeds[threadIdx.x];
    }
    __syncthreads();

    const int HW = H * H;
    const long long total = (long long)B * HW;
    const long long tid = (long long)blockIdx.x * blockDim.x + threadIdx.x;
    if (tid >= total) return;

    const int pix = (int)(tid % HW);
    const int b   = (int)(tid / HW);
    const int w   = pix % H;
    const int h   = pix / H;

    const float px = (float)w + x0[b];
    const float py = (float)h + y0[b];

    float* outb = out + (size_t)b * (size_t)(2 * L) * (size_t)HW + pix;

    #pragma unroll
    for (int l = 0; l < L; l++) {
        const float sc = s_scale[l];
        const float xn = px * sc;
        const float yn = py * sc;
        const float fx0f = floorf(xn);
        const float fy0f = floorf(yn);
        const int ix0 = (int)fx0f;
        const int iy0 = (int)fy0f;
        const float fx = xn - fx0f;
        const float fy = yn - fy0f;

        const unsigned int se  = s_seed[l];
        const unsigned int hx0 = (unsigned int)ix0 * HASH_P1;
        const unsigned int hx1 = hx0 + HASH_P1;
        const unsigned int hy0 = (unsigned int)iy0 * HASH_P2;
        const unsigned int hy1 = hy0 + HASH_P2;

        unsigned int i00, i10, i01, i11;
        if (POW2) {
            i00 = (hx0 ^ hy0 ^ se) & mask;
            i10 = (hx1 ^ hy0 ^ se) & mask;
            i01 = (hx0 ^ hy1 ^ se) & mask;
            i11 = (hx1 ^ hy1 ^ se) & mask;
        } else {
            i00 = (hx0 ^ hy0 ^ se) % T;
            i10 = (hx1 ^ hy0 ^ se) % T;
            i01 = (hx0 ^ hy1 ^ se) % T;
            i11 = (hx1 ^ hy1 ^ se) % T;
        }

        const float2 f00 = __ldg(&tables[i00]);
        const float2 f10 = __ldg(&tables[i10]);
        const float2 f01 = __ldg(&tables[i01]);
        const float2 f11 = __ldg(&tables[i11]);

        const float gx = 1.0f - fx;
        const float gy = 1.0f - fy;
        const float w00 = gx * gy;
        const float w10 = fx * gy;
        const float w01 = gx * fy;
        const float w11 = fx * fy;

        const float ex = w00 * f00.x + w10 * f10.x + w01 * f01.x + w11 * f11.x;
        const float ey = w00 * f00.y + w10 * f10.y + w01 * f01.y + w11 * f11.y;

        outb[(size_t)(2 * l)     * (size_t)HW] = ex;
        outb[(size_t)(2 * l + 1) * (size_t)HW] = ey;
    }
}

extern "C" void kernel_launch(void* const* d_in, const int* in_sizes, int n_in,
                              void* d_out, int out_size)
{
    const float*        x0     = (const float*)d_in[0];
    const float*        y0     = (const float*)d_in[1];
    const float2*       tables = (const float2*)d_in[2];
    const unsigned int* seeds  = (const unsigned int*)d_in[3];
    const float*        levelN = (const float*)d_in[4];
    const int*          tile   = (const int*)d_in[6];   // complete_tile_size scalar
    float*              out    = (float*)d_out;

    const int B = in_sizes[0];
    const int L = in_sizes[3];
    const unsigned int T = (unsigned int)(in_sizes[2] / 2);   // FEAT_DIM = 2

    const long long hw = (long long)out_size / ((long long)B * 2LL * (long long)L);
    int H = (int)(sqrt((double)hw) + 0.5);

    const bool pow2 = (T & (T - 1)) == 0;
    const unsigned int mask = T - 1;

    if (pow2 && L == 16 && (H % 2) == 0 && B <= 65535) {
        const int perb = (H / 2) * H;
        const int threads = 256;
        dim3 grid((perb + threads - 1) / threads, B);
        hashenc_2px<<<grid, threads>>>(x0, y0, tables, seeds, levelN, tile,
                                       out, H, mask);
        return;
    }

    const long long total = (long long)B * H * H;
    const int threads = 256;
    const int blocks = (int)((total + threads - 1) / threads);

    if (L == 16) {
        if (pow2)
            hashenc_kernel<16, true><<<blocks, threads>>>(x0, y0, tables, seeds, levelN,
                                                          tile, out, B, H, L, T, mask);
        else
            hashenc_kernel<16, false><<<blocks, threads>>>(x0, y0, tables, seeds, levelN,
                                                           tile, out, B, H, L, T, mask);
    } else {
        if (pow2)
            hashenc_kernel<0, true><<<blocks, threads>>>(x0, y0, tables, seeds, levelN,
                                                         tile, out, B, H, L, T, mask);
        else
            hashenc_kernel<0, false><<<blocks, threads>>>(x0, y0, tables, seeds, levelN,
                                                          tile, out, B, H, L, T, mask);
    }
}

// round 10
// speedup vs baseline: 1.0655x; 1.0655x over previous
#include <cuda_runtime.h>
#include <math.h>

// LIANetLight hash-grid encoder.
// Inputs (metadata order):
//  0: x0      float32 [B]
//  1: y0      float32 [B]
//  2: tables  float32 [T, 2]
//  3: seeds   uint32  [L]
//  4: level_N float32 [L]
//  5: memorized_crop_size (scalar)
//  6: complete_tile_size  (scalar)
// Output: float32 [B, L*2, H, W]

#define HASH_P1 2654435761u
#define HASH_P2 805459861u

__device__ __forceinline__ float read_scalar_as_float(const int* p) {
    int v = *p;
    if (v > 0 && v < (1 << 24)) return (float)v;
    return __int_as_float(v);
}

__device__ __forceinline__ void store_cs(float* p, float v) {
    asm volatile("st.global.cs.f32 [%0], %1;" :: "l"(p), "f"(v) : "memory");
}

// ---------------------------------------------------------------------------
// Direct kernel, 1 pixel/thread, 128-thread CTAs, grid=(HW/128, B).
// Same dataflow as the round-1 kernel (the only structure measured to run
// the L1tex pipe near its ceiling), minus the 64-bit div/mod prologue and
// with one fewer XOR per table index. Streaming stores keep L2 for the table.
// Requires: T power of two, L == 16, HW % 128 == 0.
// ---------------------------------------------------------------------------
__global__ void __launch_bounds__(128)
hashenc_fast(const float* __restrict__ x0,
             const float* __restrict__ y0,
             const float2* __restrict__ tables,
             const unsigned int* __restrict__ seeds,
             const float* __restrict__ levelN,
             const int* __restrict__ tile_ptr,
             float* __restrict__ out,
             int H, unsigned int mask)
{
    const int L = 16;

    __shared__ float s_scale[16];
    __shared__ unsigned int s_seed[16];
    if (threadIdx.x < L) {
        const float tf = read_scalar_as_float(tile_ptr);
        s_scale[threadIdx.x] = levelN[threadIdx.x] / tf;
        s_seed[threadIdx.x]  = seeds[threadIdx.x];
    }
    __syncthreads();

    const int HW  = H * H;
    const int b   = blockIdx.y;
    const int pix = (int)(blockIdx.x * 128u + threadIdx.x);   // < HW by grid
    const int w   = pix % H;     // H==256 -> compiles to AND
    const int h   = pix / H;     // -> SHR

    const float px = (float)w + __ldg(&x0[b]);
    const float py = (float)h + __ldg(&y0[b]);

    float* outb = out + (size_t)b * (size_t)(2 * L) * (size_t)HW + pix;

    #pragma unroll
    for (int l = 0; l < L; l++) {
        const float sc        = s_scale[l];
        const unsigned int se = s_seed[l];

        const float xn  = px * sc;
        const float fxf = floorf(xn);
        const float fx  = xn - fxf;
        const float yn  = py * sc;
        const float fyf = floorf(yn);
        const float fy  = yn - fyf;

        const unsigned int hx0 = (unsigned int)(int)fxf * HASH_P1;
        const unsigned int hx1 = hx0 + HASH_P1;        // (ix0+1)*P1 mod 2^32
        unsigned int hy0 = (unsigned int)(int)fyf * HASH_P2;
        unsigned int hy1 = hy0 + HASH_P2;              // (iy0+1)*P2 mod 2^32
        hy0 ^= se;                                     // fold seed AFTER the adds
        hy1 ^= se;

        const float2 f00 = __ldg(&tables[(hx0 ^ hy0) & mask]);
        const float2 f10 = __ldg(&tables[(hx1 ^ hy0) & mask]);
        const float2 f01 = __ldg(&tables[(hx0 ^ hy1) & mask]);
        const float2 f11 = __ldg(&tables[(hx1 ^ hy1) & mask]);

        const float gx = 1.0f - fx;
        const float gy = 1.0f - fy;
        const float w00 = gx * gy, w10 = fx * gy;
        const float w01 = gx * fy, w11 = fx * fy;

        const float ex = w00 * f00.x + w10 * f10.x + w01 * f01.x + w11 * f11.x;
        const float ey = w00 * f00.y + w10 * f10.y + w01 * f01.y + w11 * f11.y;

        store_cs(outb + (size_t)(2 * l)     * (size_t)HW, ex);
        store_cs(outb + (size_t)(2 * l + 1) * (size_t)HW, ey);
    }
}

// ---------------------------------------------------------------------------
// Generic fallback: one thread per pixel, runtime L / non-pow2 T.
// ---------------------------------------------------------------------------
template <int LFIX, bool POW2>
__global__ void __launch_bounds__(256)
hashenc_kernel(const float* __restrict__ x0,
               const float* __restrict__ y0,
               const float2* __restrict__ tables,
               const unsigned int* __restrict__ seeds,
               const float* __restrict__ levelN,
               const int* __restrict__ tile_ptr,
               float* __restrict__ out,
               int B, int H, int Lrt,
               unsigned int T, unsigned int mask)
{
    const int L = (LFIX > 0) ? LFIX : Lrt;

    __shared__ float s_scale[64];
    __shared__ unsigned int s_seed[64];
    if (threadIdx.x < L) {
        float tf = read_scalar_as_float(tile_ptr);
        s_scale[threadIdx.x] = levelN[threadIdx.x] / tf;
        s_seed[threadIdx.x]  = seeds[threadIdx.x];
    }
    __syncthreads();

    const int HW = H * H;
    const long long total = (long long)B * HW;
    const long long tid = (long long)blockIdx.x * blockDim.x + threadIdx.x;
    if (tid >= total) return;

    const int pix = (int)(tid % HW);
    const int b   = (int)(tid / HW);
    const int w   = pix % H;
    const int h   = pix / H;

    const float px = (float)w + x0[b];
    const float py = (float)h + y0[b];

    float* outb = out + (size_t)b * (size_t)(2 * L) * (size_t)HW + pix;

    #pragma unroll
    for (int l = 0; l < L; l++) {
        const float sc = s_scale[l];
        const float xn = px * sc;
        const float yn = py * sc;
        const float fx0f = floorf(xn);
        const float fy0f = floorf(yn);
        const int ix0 = (int)fx0f;
        const int iy0 = (int)fy0f;
        const float fx = xn - fx0f;
        const float fy = yn - fy0f;

        const unsigned int se  = s_seed[l];
        const unsigned int hx0 = (unsigned int)ix0 * HASH_P1;
        const unsigned int hx1 = hx0 + HASH_P1;
        const unsigned int hy0 = (unsigned int)iy0 * HASH_P2;
        const unsigned int hy1 = hy0 + HASH_P2;

        unsigned int i00, i10, i01, i11;
        if (POW2) {
            i00 = (hx0 ^ hy0 ^ se) & mask;
            i10 = (hx1 ^ hy0 ^ se) & mask;
            i01 = (hx0 ^ hy1 ^ se) & mask;
            i11 = (hx1 ^ hy1 ^ se) & mask;
        } else {
            i00 = (hx0 ^ hy0 ^ se) % T;
            i10 = (hx1 ^ hy0 ^ se) % T;
            i01 = (hx0 ^ hy1 ^ se) % T;
            i11 = (hx1 ^ hy1 ^ se) % T;
        }

        const float2 f00 = __ldg(&tables[i00]);
        const float2 f10 = __ldg(&tables[i10]);
        const float2 f01 = __ldg(&tables[i01]);
        const float2 f11 = __ldg(&tables[i11]);

        const float gx = 1.0f - fx;
        const float gy = 1.0f - fy;
        const float w00 = gx * gy;
        const float w10 = fx * gy;
        const float w01 = gx * fy;
        const float w11 = fx * fy;

        const float ex = w00 * f00.x + w10 * f10.x + w01 * f01.x + w11 * f11.x;
        const float ey = w00 * f00.y + w10 * f10.y + w01 * f01.y + w11 * f11.y;

        outb[(size_t)(2 * l)     * (size_t)HW] = ex;
        outb[(size_t)(2 * l + 1) * (size_t)HW] = ey;
    }
}

extern "C" void kernel_launch(void* const* d_in, const int* in_sizes, int n_in,
                              void* d_out, int out_size)
{
    const float*        x0     = (const float*)d_in[0];
    const float*        y0     = (const float*)d_in[1];
    const float2*       tables = (const float2*)d_in[2];
    const unsigned int* seeds  = (const unsigned int*)d_in[3];
    const float*        levelN = (const float*)d_in[4];
    const int*          tile   = (const int*)d_in[6];   // complete_tile_size scalar
    float*              out    = (float*)d_out;

    const int B = in_sizes[0];
    const int L = in_sizes[3];
    const unsigned int T = (unsigned int)(in_sizes[2] / 2);   // FEAT_DIM = 2

    const long long hw = (long long)out_size / ((long long)B * 2LL * (long long)L);
    int H = (int)(sqrt((double)hw) + 0.5);

    const bool pow2 = (T & (T - 1)) == 0;
    const unsigned int mask = T - 1;
    const int HW = H * H;

    if (pow2 && L == 16 && (HW % 128) == 0 && B <= 65535) {
        dim3 grid(HW / 128, B);
        hashenc_fast<<<grid, 128>>>(x0, y0, tables, seeds, levelN, tile,
                                    out, H, mask);
        return;
    }

    const long long total = (long long)B * HW;
    const int threads = 256;
    const int blocks = (int)((total + threads - 1) / threads);

    if (L == 16) {
        if (pow2)
            hashenc_kernel<16, true><<<blocks, threads>>>(x0, y0, tables, seeds, levelN,
                                                          tile, out, B, H, L, T, mask);
        else
            hashenc_kernel<16, false><<<blocks, threads>>>(x0, y0, tables, seeds, levelN,
                                                           tile, out, B, H, L, T, mask);
    } else {
        if (pow2)
            hashenc_kernel<0, true><<<blocks, threads>>>(x0, y0, tables, seeds, levelN,
                                                         tile, out, B, H, L, T, mask);
        else
            hashenc_kernel<0, false><<<blocks, threads>>>(x0, y0, tables, seeds, levelN,
                                                          tile, out, B, H, L, T, mask);
    }
}